// round 2
// baseline (speedup 1.0000x reference)
#include <cuda_runtime.h>
#include <math.h>

#define H      768
#define BATCH  16
#define SEQ    4096
#define NCHUNK 32
#define CHUNK  (SEQ / NCHUNK)      // 128
#define NT     256
#define PER    (H / NT)            // 3
#define NW     (NT / 32)           // 8
#define SCALE  0.03608439182435161f  // 768^-0.5
#define TN     32
#define KT     64

// ---------------- scratch (static device allocations, allowed) ----------------
__device__ float g_psum [BATCH][NCHUNK][H];
__device__ float g_pmax [BATCH][NCHUNK][H];
__device__ float g_pmin [BATCH][NCHUNK][H];
__device__ float g_pacc0[BATCH][NCHUNK][H];
__device__ float g_pacc1[BATCH][NCHUNK][H];
__device__ float g_pm   [BATCH][NCHUNK][2];
__device__ float g_pl   [BATCH][NCHUNK][2];
__device__ float g_pooled[2][BATCH][3 * H];  // [0]=trad(mean|max|min), [1]=learn(pmp0|pmp1|clf)
__device__ float g_hid   [2][BATCH][H];

__device__ __forceinline__ float4 warpRed4(float4 v) {
#pragma unroll
    for (int o = 16; o > 0; o >>= 1) {
        v.x += __shfl_down_sync(0xffffffffu, v.x, o);
        v.y += __shfl_down_sync(0xffffffffu, v.y, o);
        v.z += __shfl_down_sync(0xffffffffu, v.z, o);
        v.w += __shfl_down_sync(0xffffffffu, v.w, o);
    }
    return v;
}

// ---------------- kernel 1: fused LN + online-softmax-attn + pooling ----------------
__global__ __launch_bounds__(NT) void main_pass(
    const float* __restrict__ tokens, const int* __restrict__ lengths,
    const float* __restrict__ q, const float* __restrict__ ln_g,
    const float* __restrict__ ln_b)
{
    const int b = blockIdx.y, c = blockIdx.x, t = threadIdx.x;
    __shared__ float4 sred[NW];
    __shared__ float  sb[6];

    const int len = lengths[b];
    const int s0  = c * CHUNK;
    const int s1  = min(s0 + CHUNK, len);

    float gv[PER], lbv[PER], qg0[PER], qg1[PER];
    float4 sp = make_float4(0.f, 0.f, 0.f, 0.f);
#pragma unroll
    for (int i = 0; i < PER; i++) {
        int h = t + i * NT;
        float gg = ln_g[h], bb = ln_b[h];
        float q0 = q[h],   q1 = q[H + h];
        gv[i] = gg; lbv[i] = bb;
        qg0[i] = q0 * gg; qg1[i] = q1 * gg;
        sp.x += qg0[i]; sp.y += qg1[i];
        sp.z += q0 * bb; sp.w += q1 * bb;
    }
    sp = warpRed4(sp);
    if ((t & 31) == 0) sred[t >> 5] = sp;
    __syncthreads();
    float S0 = 0.f, S1 = 0.f, C0 = 0.f, C1 = 0.f;
    if (t == 0) {
        float4 v = sred[0];
        for (int w = 1; w < NW; w++) { float4 u = sred[w]; v.x += u.x; v.y += u.y; v.z += u.z; v.w += u.w; }
        S0 = v.x; S1 = v.y; C0 = v.z; C1 = v.w;
    }
    __syncthreads();

    float accS[PER], accMx[PER], accMn[PER], accA0[PER], accA1[PER];
#pragma unroll
    for (int i = 0; i < PER; i++) {
        accS[i] = 0.f; accA0[i] = 0.f; accA1[i] = 0.f;
        accMx[i] = -INFINITY; accMn[i] = INFINITY;
    }
    float m0 = -INFINITY, l0 = 0.f, m1 = -INFINITY, l1 = 0.f;  // thread 0 state

    const float* xbase = tokens + (size_t)b * (SEQ + 1) * H + H;  // x[b,0,:]
    float xc[PER]  = {0.f, 0.f, 0.f};
    float xnx[PER] = {0.f, 0.f, 0.f};
    if (s0 < s1) {
#pragma unroll
        for (int i = 0; i < PER; i++) xc[i] = xbase[(size_t)s0 * H + t + i * NT];
    }

    for (int s = s0; s < s1; s++) {
        // prefetch next token
        if (s + 1 < s1) {
#pragma unroll
            for (int i = 0; i < PER; i++) xnx[i] = xbase[(size_t)(s + 1) * H + t + i * NT];
        }
        float4 p = make_float4(0.f, 0.f, 0.f, 0.f);
#pragma unroll
        for (int i = 0; i < PER; i++) {
            p.x += xc[i];
            p.y = fmaf(xc[i], xc[i], p.y);
            p.z = fmaf(qg0[i], xc[i], p.z);
            p.w = fmaf(qg1[i], xc[i], p.w);
        }
        p = warpRed4(p);
        if ((t & 31) == 0) sred[t >> 5] = p;
        __syncthreads();
        if (t == 0) {
            float4 v = sred[0];
            for (int w = 1; w < NW; w++) { float4 u = sred[w]; v.x += u.x; v.y += u.y; v.z += u.z; v.w += u.w; }
            float mu   = v.x * (1.f / H);
            float var  = v.y * (1.f / H) - mu * mu;
            float rstd = rsqrtf(var + 1e-5f);
            float z0 = (rstd * (v.z - mu * S0) + C0) * SCALE;
            float z1 = (rstd * (v.w - mu * S1) + C1) * SCALE;
            float nm0 = fmaxf(m0, z0);
            float f0  = __expf(m0 - nm0);
            float w0  = __expf(z0 - nm0);
            l0 = l0 * f0 + w0; m0 = nm0;
            float nm1 = fmaxf(m1, z1);
            float f1  = __expf(m1 - nm1);
            float w1  = __expf(z1 - nm1);
            l1 = l1 * f1 + w1; m1 = nm1;
            sb[0] = mu; sb[1] = rstd; sb[2] = f0; sb[3] = w0; sb[4] = f1; sb[5] = w1;
        }
        __syncthreads();
        float mu = sb[0], rstd = sb[1], f0 = sb[2], w0 = sb[3], f1 = sb[4], w1 = sb[5];
#pragma unroll
        for (int i = 0; i < PER; i++) {
            float x = xc[i];
            accS[i] += x;
            accMx[i] = fmaxf(accMx[i], x);
            accMn[i] = fminf(accMn[i], x);
            float xn = fmaf((x - mu) * rstd, gv[i], lbv[i]);
            accA0[i] = fmaf(w0, xn, accA0[i] * f0);
            accA1[i] = fmaf(w1, xn, accA1[i] * f1);
            xc[i] = xnx[i];
        }
    }

#pragma unroll
    for (int i = 0; i < PER; i++) {
        int h = t + i * NT;
        g_psum [b][c][h] = accS[i];
        g_pmax [b][c][h] = accMx[i];
        g_pmin [b][c][h] = accMn[i];
        g_pacc0[b][c][h] = accA0[i];
        g_pacc1[b][c][h] = accA1[i];
    }
    if (t == 0) {
        g_pm[b][c][0] = m0; g_pl[b][c][0] = l0;
        g_pm[b][c][1] = m1; g_pl[b][c][1] = l1;
    }
}

// ---------------- kernel 2: merge partials, build pooled vectors ----------------
__global__ __launch_bounds__(NT) void combine_pass(
    const float* __restrict__ tokens, const int* __restrict__ lengths)
{
    const int b = blockIdx.x, t = threadIdx.x;
    __shared__ float w0c[NCHUNK], w1c[NCHUNK];
    if (t == 0) {
        float M0 = -INFINITY, M1 = -INFINITY;
        for (int c = 0; c < NCHUNK; c++) {
            M0 = fmaxf(M0, g_pm[b][c][0]);
            M1 = fmaxf(M1, g_pm[b][c][1]);
        }
        float L0 = 0.f, L1 = 0.f;
        for (int c = 0; c < NCHUNK; c++) {
            L0 += g_pl[b][c][0] * __expf(g_pm[b][c][0] - M0);
            L1 += g_pl[b][c][1] * __expf(g_pm[b][c][1] - M1);
        }
        float iL0 = 1.f / L0, iL1 = 1.f / L1;
        for (int c = 0; c < NCHUNK; c++) {
            w0c[c] = __expf(g_pm[b][c][0] - M0) * iL0;
            w1c[c] = __expf(g_pm[b][c][1] - M1) * iL1;
        }
    }
    __syncthreads();
    const float inv_len = 1.f / (float)lengths[b];
#pragma unroll
    for (int i = 0; i < PER; i++) {
        int h = t + i * NT;
        float sm = 0.f, mx = -INFINITY, mn = INFINITY, a0 = 0.f, a1 = 0.f;
        for (int c = 0; c < NCHUNK; c++) {
            sm += g_psum[b][c][h];
            mx = fmaxf(mx, g_pmax[b][c][h]);
            mn = fminf(mn, g_pmin[b][c][h]);
            a0 = fmaf(g_pacc0[b][c][h], w0c[c], a0);
            a1 = fmaf(g_pacc1[b][c][h], w1c[c], a1);
        }
        g_pooled[0][b][h]         = sm * inv_len;
        g_pooled[0][b][H + h]     = mx;
        g_pooled[0][b][2 * H + h] = mn;
        g_pooled[1][b][h]         = a0;
        g_pooled[1][b][H + h]     = a1;
        g_pooled[1][b][2 * H + h] = tokens[(size_t)b * (SEQ + 1) * H + h];  // clf
    }
}

// ---------------- kernels 3/4: small batched GEMMs (each weight read once) ----------------
template <int K, bool LAYERA>
__global__ __launch_bounds__(256) void mlp_gemm(
    const float* __restrict__ W0, const float* __restrict__ W1,
    const float* __restrict__ bias0, const float* __restrict__ bias1,
    float* __restrict__ extOut)
{
    const int br   = blockIdx.y;
    const int j0   = blockIdx.x * TN;
    const int t    = threadIdx.x;
    const int lane = t & (TN - 1);
    const int rg   = t / TN;  // 0..7, 2 rows each

    const float* P    = LAYERA ? &g_pooled[br][0][0] : &g_hid[br][0][0];
    const float* W    = br ? W1 : W0;
    const float* bias = br ? bias1 : bias0;

    __shared__ float sW[KT][TN];
    __shared__ float sP[BATCH][KT];

    float acc0 = 0.f, acc1 = 0.f;
    for (int k0 = 0; k0 < K; k0 += KT) {
        __syncthreads();
#pragma unroll
        for (int r = 0; r < (KT * TN) / 256; r++) {
            int idx = t + r * 256;
            sW[idx / TN][idx % TN] = W[(size_t)(k0 + idx / TN) * H + j0 + (idx % TN)];
        }
#pragma unroll
        for (int r = 0; r < (BATCH * KT) / 256; r++) {
            int idx = t + r * 256;
            sP[idx / KT][idx % KT] = P[(size_t)(idx / KT) * K + k0 + (idx % KT)];
        }
        __syncthreads();
#pragma unroll
        for (int kk = 0; kk < KT; kk++) {
            float wv = sW[kk][lane];
            acc0 = fmaf(sP[2 * rg][kk],     wv, acc0);
            acc1 = fmaf(sP[2 * rg + 1][kk], wv, acc1);
        }
    }
    float bj = bias[j0 + lane];
    float v0 = acc0 + bj, v1 = acc1 + bj;
    if (LAYERA) {
        v0 = 0.5f * v0 * (1.f + erff(v0 * 0.7071067811865476f));
        v1 = 0.5f * v1 * (1.f + erff(v1 * 0.7071067811865476f));
        g_hid[br][2 * rg][j0 + lane]     = v0;
        g_hid[br][2 * rg + 1][j0 + lane] = v1;
    } else {
        extOut[(size_t)(2 * rg) * (2 * H) + br * H + j0 + lane]     = v0;
        extOut[(size_t)(2 * rg + 1) * (2 * H) + br * H + j0 + lane] = v1;
    }
}

// ---------------- launch ----------------
extern "C" void kernel_launch(void* const* d_in, const int* in_sizes, int n_in,
                              void* d_out, int out_size)
{
    const float* tokens = (const float*)d_in[0];
    const int*   lengths= (const int*)  d_in[1];
    const float* q      = (const float*)d_in[2];
    const float* ln_g   = (const float*)d_in[3];
    const float* ln_b   = (const float*)d_in[4];
    const float* w1a    = (const float*)d_in[5];
    const float* b1a    = (const float*)d_in[6];
    const float* w1b    = (const float*)d_in[7];
    const float* b1b    = (const float*)d_in[8];
    const float* w2a    = (const float*)d_in[9];
    const float* b2a    = (const float*)d_in[10];
    const float* w2b    = (const float*)d_in[11];
    const float* b2b    = (const float*)d_in[12];
    float* out = (float*)d_out;

    main_pass<<<dim3(NCHUNK, BATCH), NT>>>(tokens, lengths, q, ln_g, ln_b);
    combine_pass<<<BATCH, NT>>>(tokens, lengths);
    mlp_gemm<3 * H, true ><<<dim3(H / TN, 2), 256>>>(w1a, w2a, b1a, b2a, nullptr);
    mlp_gemm<H,     false><<<dim3(H / TN, 2), 256>>>(w1b, w2b, b1b, b2b, out);
}

// round 3
// speedup vs baseline: 1.2382x; 1.2382x over previous
#include <cuda_runtime.h>
#include <math.h>

#define H      768
#define BATCH  16
#define SEQ    4096
#define NCHUNK 32
#define CHUNK  (SEQ / NCHUNK)      // 128
#define NT     256
#define PER    (H / NT)            // 3
#define NW     (NT / 32)           // 8
#define G      8                   // tokens per group
#define SCALE  0.03608439182435161f  // 768^-0.5
#define KSPLIT 6
#define NSLOT  (KSPLIT * 16)       // 96 partial slots per (branch)

// ---------------- scratch (static device arrays, allowed) ----------------
__device__ float g_psum [BATCH][NCHUNK][H];
__device__ float g_pmax [BATCH][NCHUNK][H];
__device__ float g_pmin [BATCH][NCHUNK][H];
__device__ float g_pacc0[BATCH][NCHUNK][H];
__device__ float g_pacc1[BATCH][NCHUNK][H];
__device__ float g_pm   [BATCH][NCHUNK][2];
__device__ float g_pl   [BATCH][NCHUNK][2];
__device__ float g_pooled[2][BATCH][3 * H];  // [0]=trad(mean|max|min), [1]=learn(pmp0|pmp1|clf)
__device__ float g_hid   [2][BATCH][H];
__device__ float g_partA [2][NSLOT][BATCH][H];
__device__ float g_partB [2][NSLOT][BATCH][H];

__device__ __forceinline__ float4 warpRed4(float4 v) {
#pragma unroll
    for (int o = 16; o > 0; o >>= 1) {
        v.x += __shfl_down_sync(0xffffffffu, v.x, o);
        v.y += __shfl_down_sync(0xffffffffu, v.y, o);
        v.z += __shfl_down_sync(0xffffffffu, v.z, o);
        v.w += __shfl_down_sync(0xffffffffu, v.w, o);
    }
    return v;
}

// ---------------- kernel 1: fused LN + online-softmax-attn + pooling (8-token groups) ----
__global__ __launch_bounds__(NT) void main_pass(
    const float* __restrict__ tokens, const int* __restrict__ lengths,
    const float* __restrict__ q, const float* __restrict__ ln_g,
    const float* __restrict__ ln_b)
{
    const int b = blockIdx.y, c = blockIdx.x, t = threadIdx.x;
    const int wid = t >> 5, lane = t & 31;
    __shared__ float4 sredG[NW][G];
    __shared__ float  smu[G], srstd[G], sw0[G], sw1[G], sf01[2];
    __shared__ float  sSC[4];

    const int len = lengths[b];
    const int s0  = c * CHUNK;
    const int s1  = min(s0 + CHUNK, len);

    float gv[PER], lbv[PER], qg0[PER], qg1[PER];
    {
        float4 sp = make_float4(0.f, 0.f, 0.f, 0.f);
#pragma unroll
        for (int i = 0; i < PER; i++) {
            int h = t + i * NT;
            float gg = ln_g[h], bb = ln_b[h];
            float q0 = q[h],   q1 = q[H + h];
            gv[i] = gg; lbv[i] = bb;
            qg0[i] = q0 * gg; qg1[i] = q1 * gg;
            sp.x += qg0[i]; sp.y += qg1[i];
            sp.z += q0 * bb; sp.w += q1 * bb;
        }
        sp = warpRed4(sp);
        if (lane == 0) sredG[wid][0] = sp;
        __syncthreads();
        if (t == 0) {
            float4 v = sredG[0][0];
            for (int w = 1; w < NW; w++) {
                float4 u = sredG[w][0]; v.x += u.x; v.y += u.y; v.z += u.z; v.w += u.w;
            }
            sSC[0] = v.x; sSC[1] = v.y; sSC[2] = v.z; sSC[3] = v.w;
        }
        __syncthreads();
    }
    const float S0 = sSC[0], S1 = sSC[1], C0 = sSC[2], C1 = sSC[3];

    float accS[PER], accMx[PER], accMn[PER], accA0[PER], accA1[PER];
#pragma unroll
    for (int i = 0; i < PER; i++) {
        accS[i] = 0.f; accA0[i] = 0.f; accA1[i] = 0.f;
        accMx[i] = -INFINITY; accMn[i] = INFINITY;
    }
    float m0 = -INFINITY, l0 = 0.f, m1 = -INFINITY, l1 = 0.f;  // valid in lanes 0..7 of warp 0

    if (s0 < s1) {
        const float* xbase = tokens + (size_t)b * (SEQ + 1) * H + H;  // x[b,0,:]
        float xa[G][PER];
#pragma unroll
        for (int g = 0; g < G; g++) {
            int s = min(s0 + g, s1 - 1);
#pragma unroll
            for (int i = 0; i < PER; i++) xa[g][i] = xbase[(size_t)s * H + t + i * NT];
        }

        for (int base = s0; base < s1; base += G) {
            // ---- stage A: per-thread partials for all 8 tokens ----
            float4 p[G];
#pragma unroll
            for (int g = 0; g < G; g++) {
                float4 v = make_float4(0.f, 0.f, 0.f, 0.f);
#pragma unroll
                for (int i = 0; i < PER; i++) {
                    float x = xa[g][i];
                    v.x += x;
                    v.y = fmaf(x, x, v.y);
                    v.z = fmaf(qg0[i], x, v.z);
                    v.w = fmaf(qg1[i], x, v.w);
                }
                p[g] = v;
            }
            // prefetch next group while reductions run
            float xb[G][PER];
            const int nb = base + G;
            if (nb < s1) {
#pragma unroll
                for (int g = 0; g < G; g++) {
                    int s = min(nb + g, s1 - 1);
#pragma unroll
                    for (int i = 0; i < PER; i++) xb[g][i] = xbase[(size_t)s * H + t + i * NT];
                }
            } else {
#pragma unroll
                for (int g = 0; g < G; g++)
#pragma unroll
                    for (int i = 0; i < PER; i++) xb[g][i] = 0.f;
            }
#pragma unroll
            for (int g = 0; g < G; g++) p[g] = warpRed4(p[g]);
            if (lane == 0) {
#pragma unroll
                for (int g = 0; g < G; g++) sredG[wid][g] = p[g];
            }
            __syncthreads();

            // ---- stage B: lanes 0..7 of warp 0, one token each ----
            if (t < G) {
                float4 v = sredG[0][t];
#pragma unroll
                for (int w = 1; w < NW; w++) {
                    float4 u = sredG[w][t]; v.x += u.x; v.y += u.y; v.z += u.z; v.w += u.w;
                }
                const bool valid = (base + t) < s1;
                float mu   = v.x * (1.f / H);
                float var  = v.y * (1.f / H) - mu * mu;
                float rstd = rsqrtf(var + 1e-5f);
                float z0 = valid ? (rstd * (v.z - mu * S0) + C0) * SCALE : -INFINITY;
                float z1 = valid ? (rstd * (v.w - mu * S1) + C1) * SCALE : -INFINITY;
                float gm0 = z0, gm1 = z1;
#pragma unroll
                for (int o = 4; o > 0; o >>= 1) {
                    gm0 = fmaxf(gm0, __shfl_xor_sync(0xffu, gm0, o, 8));
                    gm1 = fmaxf(gm1, __shfl_xor_sync(0xffu, gm1, o, 8));
                }
                float nm0 = fmaxf(m0, gm0), nm1 = fmaxf(m1, gm1);
                float f0 = __expf(m0 - nm0), f1 = __expf(m1 - nm1);
                float w0g = valid ? __expf(z0 - nm0) : 0.f;
                float w1g = valid ? __expf(z1 - nm1) : 0.f;
                float ws0 = w0g, ws1 = w1g;
#pragma unroll
                for (int o = 4; o > 0; o >>= 1) {
                    ws0 += __shfl_xor_sync(0xffu, ws0, o, 8);
                    ws1 += __shfl_xor_sync(0xffu, ws1, o, 8);
                }
                l0 = l0 * f0 + ws0; m0 = nm0;
                l1 = l1 * f1 + ws1; m1 = nm1;
                smu[t] = mu; srstd[t] = rstd; sw0[t] = w0g; sw1[t] = w1g;
                if (t == 0) { sf01[0] = f0; sf01[1] = f1; }
            }
            __syncthreads();

            // ---- stage C: accumulate all 8 tokens ----
            const float f0 = sf01[0], f1 = sf01[1];
#pragma unroll
            for (int i = 0; i < PER; i++) { accA0[i] *= f0; accA1[i] *= f1; }
            const int gmax = min(G, s1 - base);
#pragma unroll
            for (int g = 0; g < G; g++) {
                if (g < gmax) {
                    const float mu = smu[g], rstd = srstd[g], w0 = sw0[g], w1 = sw1[g];
#pragma unroll
                    for (int i = 0; i < PER; i++) {
                        float x = xa[g][i];
                        accS[i] += x;
                        accMx[i] = fmaxf(accMx[i], x);
                        accMn[i] = fminf(accMn[i], x);
                        float xn = fmaf((x - mu) * rstd, gv[i], lbv[i]);
                        accA0[i] = fmaf(w0, xn, accA0[i]);
                        accA1[i] = fmaf(w1, xn, accA1[i]);
                    }
                }
            }
#pragma unroll
            for (int g = 0; g < G; g++)
#pragma unroll
                for (int i = 0; i < PER; i++) xa[g][i] = xb[g][i];
        }
    }

#pragma unroll
    for (int i = 0; i < PER; i++) {
        int h = t + i * NT;
        g_psum [b][c][h] = accS[i];
        g_pmax [b][c][h] = accMx[i];
        g_pmin [b][c][h] = accMn[i];
        g_pacc0[b][c][h] = accA0[i];
        g_pacc1[b][c][h] = accA1[i];
    }
    if (t == 0) {
        g_pm[b][c][0] = m0; g_pl[b][c][0] = l0;
        g_pm[b][c][1] = m1; g_pl[b][c][1] = l1;
    }
}

// ---------------- kernel 2: merge partials, build pooled vectors (split over h) --------
__global__ __launch_bounds__(NT) void combine_pass(
    const float* __restrict__ tokens, const int* __restrict__ lengths)
{
    const int b = blockIdx.x, t = threadIdx.x;
    const int h = blockIdx.y * NT + t;
    __shared__ float w0c[NCHUNK], w1c[NCHUNK];
    if (t == 0) {
        float M0 = -INFINITY, M1 = -INFINITY;
        for (int c = 0; c < NCHUNK; c++) {
            M0 = fmaxf(M0, g_pm[b][c][0]);
            M1 = fmaxf(M1, g_pm[b][c][1]);
        }
        float L0 = 0.f, L1 = 0.f;
        for (int c = 0; c < NCHUNK; c++) {
            L0 += g_pl[b][c][0] * __expf(g_pm[b][c][0] - M0);
            L1 += g_pl[b][c][1] * __expf(g_pm[b][c][1] - M1);
        }
        float iL0 = 1.f / L0, iL1 = 1.f / L1;
        for (int c = 0; c < NCHUNK; c++) {
            w0c[c] = __expf(g_pm[b][c][0] - M0) * iL0;
            w1c[c] = __expf(g_pm[b][c][1] - M1) * iL1;
        }
    }
    __syncthreads();
    const float inv_len = 1.f / (float)lengths[b];
    float sm = 0.f, mx = -INFINITY, mn = INFINITY, a0 = 0.f, a1 = 0.f;
#pragma unroll 4
    for (int c = 0; c < NCHUNK; c++) {
        sm += g_psum[b][c][h];
        mx = fmaxf(mx, g_pmax[b][c][h]);
        mn = fminf(mn, g_pmin[b][c][h]);
        a0 = fmaf(g_pacc0[b][c][h], w0c[c], a0);
        a1 = fmaf(g_pacc1[b][c][h], w1c[c], a1);
    }
    g_pooled[0][b][h]         = sm * inv_len;
    g_pooled[0][b][H + h]     = mx;
    g_pooled[0][b][2 * H + h] = mn;
    g_pooled[1][b][h]         = a0;
    g_pooled[1][b][H + h]     = a1;
    g_pooled[1][b][2 * H + h] = tokens[(size_t)b * (SEQ + 1) * H + h];  // clf
}

// ---------------- kernels 3/5: split-K partial GEMMs ----------------
// out_partial[br][slot][m][j] over k-range of slot. Each block: 64 j cols, KC k's.
// Threads: 16 j-quads x 16 k-groups. W streamed as float4 (64 FMA per LDG.128).
template <int K, int KC, bool LAYERA>
__global__ __launch_bounds__(256) void gemm_part(
    const float* __restrict__ W0, const float* __restrict__ W1)
{
    const int br = blockIdx.z;
    const int j0 = blockIdx.x * 64;
    const int k0 = blockIdx.y * KC;
    const int t  = threadIdx.x;
    const float* W = br ? W1 : W0;
    const float* P = LAYERA ? &g_pooled[br][0][0] : &g_hid[br][0][0];

    __shared__ float sP[KC][20];  // padded row (80B) to keep banks spread + 16B aligned
    for (int idx = t; idx < BATCH * KC; idx += 256) {
        int m = idx / KC, k = idx % KC;
        sP[k][m] = P[(size_t)m * K + k0 + k];
    }
    __syncthreads();

    const int jj = (t & 15) * 4;
    const int kg = t >> 4;                 // 0..15
    const int kb = kg * (KC / 16);
    float4 acc[BATCH];
#pragma unroll
    for (int m = 0; m < BATCH; m++) acc[m] = make_float4(0.f, 0.f, 0.f, 0.f);

    const float* Wp = W + (size_t)(k0 + kb) * H + j0 + jj;
#pragma unroll 4
    for (int k = 0; k < KC / 16; k++) {
        const float4 w = *(const float4*)(Wp + (size_t)k * H);
        const float* prow = &sP[kb + k][0];
#pragma unroll
        for (int m4 = 0; m4 < BATCH; m4 += 4) {
            const float4 pv = *(const float4*)(prow + m4);
            float pm[4] = {pv.x, pv.y, pv.z, pv.w};
#pragma unroll
            for (int u = 0; u < 4; u++) {
                acc[m4 + u].x = fmaf(pm[u], w.x, acc[m4 + u].x);
                acc[m4 + u].y = fmaf(pm[u], w.y, acc[m4 + u].y);
                acc[m4 + u].z = fmaf(pm[u], w.z, acc[m4 + u].z);
                acc[m4 + u].w = fmaf(pm[u], w.w, acc[m4 + u].w);
            }
        }
    }

    const int slot = blockIdx.y * 16 + kg;
    float* part = LAYERA ? &g_partA[br][slot][0][0] : &g_partB[br][slot][0][0];
#pragma unroll
    for (int m = 0; m < BATCH; m++)
        *(float4*)&part[(size_t)m * H + j0 + jj] = acc[m];
}

// ---------------- kernel 4: reduce partials + bias + GELU -> g_hid ----------------
__global__ __launch_bounds__(256) void act_pass(
    const float* __restrict__ b1a, const float* __restrict__ b2a)
{
    const int id = blockIdx.x * 256 + threadIdx.x;  // 2*16*768 total
    const int j  = id % H;
    const int m  = (id / H) % BATCH;
    const int br = id / (H * BATCH);
    float s = 0.f;
#pragma unroll 8
    for (int sl = 0; sl < NSLOT; sl++) s += g_partA[br][sl][m][j];
    s += (br ? b2a : b1a)[j];
    float v = 0.5f * s * (1.f + erff(s * 0.7071067811865476f));
    g_hid[br][m][j] = v;
}

// ---------------- kernel 6: reduce partials + bias -> output ----------------
__global__ __launch_bounds__(256) void final_pass(
    const float* __restrict__ b1b, const float* __restrict__ b2b,
    float* __restrict__ out)
{
    const int id = blockIdx.x * 256 + threadIdx.x;
    const int j  = id % H;
    const int m  = (id / H) % BATCH;
    const int br = id / (H * BATCH);
    float s = 0.f;
#pragma unroll 8
    for (int sl = 0; sl < NSLOT; sl++) s += g_partB[br][sl][m][j];
    s += (br ? b2b : b1b)[j];
    out[(size_t)m * (2 * H) + br * H + j] = s;
}

// ---------------- launch ----------------
extern "C" void kernel_launch(void* const* d_in, const int* in_sizes, int n_in,
                              void* d_out, int out_size)
{
    const float* tokens = (const float*)d_in[0];
    const int*   lengths= (const int*)  d_in[1];
    const float* q      = (const float*)d_in[2];
    const float* ln_g   = (const float*)d_in[3];
    const float* ln_b   = (const float*)d_in[4];
    const float* w1a    = (const float*)d_in[5];
    const float* b1a    = (const float*)d_in[6];
    const float* w1b    = (const float*)d_in[7];
    const float* b1b    = (const float*)d_in[8];
    const float* w2a    = (const float*)d_in[9];
    const float* b2a    = (const float*)d_in[10];
    const float* w2b    = (const float*)d_in[11];
    const float* b2b    = (const float*)d_in[12];
    float* out = (float*)d_out;

    main_pass<<<dim3(NCHUNK, BATCH), NT>>>(tokens, lengths, q, ln_g, ln_b);
    combine_pass<<<dim3(BATCH, PER), NT>>>(tokens, lengths);
    gemm_part<3 * H, 3 * H / KSPLIT, true ><<<dim3(H / 64, KSPLIT, 2), 256>>>(w1a, w2a);
    act_pass<<<(2 * BATCH * H) / 256, 256>>>(b1a, b2a);
    gemm_part<H, H / KSPLIT, false><<<dim3(H / 64, KSPLIT, 2), 256>>>(w1b, w2b);
    final_pass<<<(2 * BATCH * H) / 256, 256>>>(b1b, b2b, out);
}

// round 5
// speedup vs baseline: 2.3617x; 1.9074x over previous
#include <cuda_runtime.h>
#include <math.h>

#define H      768
#define BATCH  16
#define SEQ    4096
#define NCHUNK 32
#define CHUNK  (SEQ / NCHUNK)      // 128
#define NT     192                 // main_pass threads (768/4)
#define NW     (NT / 32)           // 6 warps
#define G      8                   // tokens per group
#define SCALE  0.03608439182435161f  // 768^-0.5
#define KSPLIT 6

// ---------------- scratch (static device arrays, allowed) ----------------
__device__ float g_psum [BATCH][NCHUNK][H];
__device__ float g_pmax [BATCH][NCHUNK][H];
__device__ float g_pmin [BATCH][NCHUNK][H];
__device__ float g_pacc0[BATCH][NCHUNK][H];
__device__ float g_pacc1[BATCH][NCHUNK][H];
__device__ float g_pm   [BATCH][NCHUNK][2];
__device__ float g_pl   [BATCH][NCHUNK][2];
__device__ float g_pooled[2][BATCH][3 * H];  // [0]=trad(mean|max|min), [1]=learn(pmp0|pmp1|clf)
__device__ float g_partA [2][KSPLIT][BATCH][H];
__device__ float g_partB [2][KSPLIT][BATCH][H];
__device__ float g_hid   [2][BATCH][H];

// ---------------- kernel 1: fused LN + online-softmax-attn + pooling ----------------
__global__ __launch_bounds__(NT, 2) void main_pass(
    const float* __restrict__ tokens, const int* __restrict__ lengths,
    const float* __restrict__ q, const float* __restrict__ ln_g,
    const float* __restrict__ ln_b)
{
    const int b = blockIdx.y, c = blockIdx.x, t = threadIdx.x;
    const int wid = t >> 5, lane = t & 31;
    const int h0 = 4 * t;
    __shared__ float  sredS[NW][32];
    __shared__ float4 sred4[NW];

    const int len = lengths[b];
    const int s0  = c * CHUNK;
    const int s1  = min(s0 + CHUNK, len);

    const float4 gv  = *(const float4*)&ln_g[h0];
    const float4 lbv = *(const float4*)&ln_b[h0];
    const float4 q0v = *(const float4*)&q[h0];
    const float4 q1v = *(const float4*)&q[H + h0];
    const float4 qg0 = make_float4(q0v.x * gv.x, q0v.y * gv.y, q0v.z * gv.z, q0v.w * gv.w);
    const float4 qg1 = make_float4(q1v.x * gv.x, q1v.y * gv.y, q1v.z * gv.z, q1v.w * gv.w);

    // block-wide constants S0,S1,C0,C1
    float S0, S1, C0, C1;
    {
        float a = (qg0.x + qg0.y) + (qg0.z + qg0.w);
        float d = (qg1.x + qg1.y) + (qg1.z + qg1.w);
        float e = fmaf(q0v.x, lbv.x, fmaf(q0v.y, lbv.y, fmaf(q0v.z, lbv.z, q0v.w * lbv.w)));
        float f = fmaf(q1v.x, lbv.x, fmaf(q1v.y, lbv.y, fmaf(q1v.z, lbv.z, q1v.w * lbv.w)));
#pragma unroll
        for (int o = 16; o > 0; o >>= 1) {
            a += __shfl_xor_sync(0xffffffffu, a, o);
            d += __shfl_xor_sync(0xffffffffu, d, o);
            e += __shfl_xor_sync(0xffffffffu, e, o);
            f += __shfl_xor_sync(0xffffffffu, f, o);
        }
        if (lane == 0) sred4[wid] = make_float4(a, d, e, f);
        __syncthreads();
        float4 v = sred4[0];
#pragma unroll
        for (int w = 1; w < NW; w++) {
            float4 u = sred4[w]; v.x += u.x; v.y += u.y; v.z += u.z; v.w += u.w;
        }
        S0 = v.x; S1 = v.y; C0 = v.z; C1 = v.w;
        __syncthreads();
    }

    float4 accS  = make_float4(0.f, 0.f, 0.f, 0.f);
    float4 accA0 = make_float4(0.f, 0.f, 0.f, 0.f);
    float4 accA1 = make_float4(0.f, 0.f, 0.f, 0.f);
    float4 accMx = make_float4(-INFINITY, -INFINITY, -INFINITY, -INFINITY);
    float4 accMn = make_float4( INFINITY,  INFINITY,  INFINITY,  INFINITY);
    float m0 = -INFINITY, l0 = 0.f, m1 = -INFINITY, l1 = 0.f;

    if (s0 < s1) {
        const float* xbase = tokens + (size_t)b * (SEQ + 1) * H + H;
        float4 xa[G];
#pragma unroll
        for (int g = 0; g < G; g++) {
            int s = min(s0 + g, s1 - 1);
            xa[g] = *(const float4*)&xbase[(size_t)s * H + h0];
        }

        for (int base = s0; base < s1; base += G) {
            // ---- stage A: per-thread partials, packed v[4g+k] ----
            float v[32];
#pragma unroll
            for (int g = 0; g < G; g++) {
                float4 x = xa[g];
                v[4 * g + 0] = (x.x + x.y) + (x.z + x.w);
                v[4 * g + 1] = fmaf(x.x, x.x, fmaf(x.y, x.y, fmaf(x.z, x.z, x.w * x.w)));
                v[4 * g + 2] = fmaf(qg0.x, x.x, fmaf(qg0.y, x.y, fmaf(qg0.z, x.z, qg0.w * x.w)));
                v[4 * g + 3] = fmaf(qg1.x, x.x, fmaf(qg1.y, x.y, fmaf(qg1.z, x.z, qg1.w * x.w)));
            }
            // prefetch next group (overlaps reduction latency)
            float4 xb[G];
            const int nb = base + G;
            if (nb < s1) {
#pragma unroll
                for (int g = 0; g < G; g++) {
                    int s = min(nb + g, s1 - 1);
                    xb[g] = *(const float4*)&xbase[(size_t)s * H + h0];
                }
            } else {
#pragma unroll
                for (int g = 0; g < G; g++) xb[g] = make_float4(0.f, 0.f, 0.f, 0.f);
            }

            // ---- warp transpose reduce: lane L ends with warp-total of v[L] ----
#pragma unroll
            for (int off = 16, n = 32; off >= 1; off >>= 1, n >>= 1) {
                const bool hi = (lane & off) != 0;
#pragma unroll
                for (int i = 0; i < 32; i++) {   // only i < n/2 active; guarded below
                    if (i < n / 2) {
                        float a = v[i], bvv = v[i + n / 2];
                        float send = hi ? a : bvv;
                        float keep = hi ? bvv : a;
                        v[i] = keep + __shfl_xor_sync(0xffffffffu, send, off);
                    }
                }
            }
            sredS[wid][lane] = v[0];
            __syncthreads();

            // ---- stage B: redundant per warp; token g8 = lane & 7 ----
            const int g8 = lane & 7;
            float sx = 0.f, sq = 0.f, d0 = 0.f, d1 = 0.f;
#pragma unroll
            for (int w = 0; w < NW; w++) {
                sx += sredS[w][4 * g8 + 0];
                sq += sredS[w][4 * g8 + 1];
                d0 += sredS[w][4 * g8 + 2];
                d1 += sredS[w][4 * g8 + 3];
            }
            const bool valid = (base + g8) < s1;
            float mu   = sx * (1.f / H);
            float var  = sq * (1.f / H) - mu * mu;
            float rstd = rsqrtf(var + 1e-5f);
            float z0 = valid ? (rstd * (d0 - mu * S0) + C0) * SCALE : -INFINITY;
            float z1 = valid ? (rstd * (d1 - mu * S1) + C1) * SCALE : -INFINITY;
            float gm0 = z0, gm1 = z1;
#pragma unroll
            for (int o = 16; o > 0; o >>= 1) {
                gm0 = fmaxf(gm0, __shfl_xor_sync(0xffffffffu, gm0, o));
                gm1 = fmaxf(gm1, __shfl_xor_sync(0xffffffffu, gm1, o));
            }
            float nm0 = fmaxf(m0, gm0), nm1 = fmaxf(m1, gm1);
            float f0 = __expf(m0 - nm0), f1 = __expf(m1 - nm1);
            float w0v = valid ? __expf(z0 - nm0) : 0.f;
            float w1v = valid ? __expf(z1 - nm1) : 0.f;
            float ws0 = w0v, ws1 = w1v;
#pragma unroll
            for (int o = 16; o > 0; o >>= 1) {
                ws0 += __shfl_xor_sync(0xffffffffu, ws0, o);
                ws1 += __shfl_xor_sync(0xffffffffu, ws1, o);
            }
            l0 = l0 * f0 + ws0 * 0.25f; m0 = nm0;   // tokens replicated 4x across warp
            l1 = l1 * f1 + ws1 * 0.25f; m1 = nm1;

            // ---- stage C: accumulate 8 tokens ----
            accA0.x *= f0; accA0.y *= f0; accA0.z *= f0; accA0.w *= f0;
            accA1.x *= f1; accA1.y *= f1; accA1.z *= f1; accA1.w *= f1;
            const int gmax = min(G, s1 - base);
#pragma unroll
            for (int g = 0; g < G; g++) {
                float mug = __shfl_sync(0xffffffffu, mu,   g);
                float rsg = __shfl_sync(0xffffffffu, rstd, g);
                float w0g = __shfl_sync(0xffffffffu, w0v,  g);
                float w1g = __shfl_sync(0xffffffffu, w1v,  g);
                if (g < gmax) {
                    float4 x = xa[g];
                    accS.x += x.x; accS.y += x.y; accS.z += x.z; accS.w += x.w;
                    accMx.x = fmaxf(accMx.x, x.x); accMx.y = fmaxf(accMx.y, x.y);
                    accMx.z = fmaxf(accMx.z, x.z); accMx.w = fmaxf(accMx.w, x.w);
                    accMn.x = fminf(accMn.x, x.x); accMn.y = fminf(accMn.y, x.y);
                    accMn.z = fminf(accMn.z, x.z); accMn.w = fminf(accMn.w, x.w);
                    float xn0 = fmaf((x.x - mug) * rsg, gv.x, lbv.x);
                    float xn1 = fmaf((x.y - mug) * rsg, gv.y, lbv.y);
                    float xn2 = fmaf((x.z - mug) * rsg, gv.z, lbv.z);
                    float xn3 = fmaf((x.w - mug) * rsg, gv.w, lbv.w);
                    accA0.x = fmaf(w0g, xn0, accA0.x); accA0.y = fmaf(w0g, xn1, accA0.y);
                    accA0.z = fmaf(w0g, xn2, accA0.z); accA0.w = fmaf(w0g, xn3, accA0.w);
                    accA1.x = fmaf(w1g, xn0, accA1.x); accA1.y = fmaf(w1g, xn1, accA1.y);
                    accA1.z = fmaf(w1g, xn2, accA1.z); accA1.w = fmaf(w1g, xn3, accA1.w);
                }
            }
#pragma unroll
            for (int g = 0; g < G; g++) xa[g] = xb[g];
            __syncthreads();
        }
    }

    *(float4*)&g_psum [b][c][h0] = accS;
    *(float4*)&g_pmax [b][c][h0] = accMx;
    *(float4*)&g_pmin [b][c][h0] = accMn;
    *(float4*)&g_pacc0[b][c][h0] = accA0;
    *(float4*)&g_pacc1[b][c][h0] = accA1;
    if (t == 0) {
        g_pm[b][c][0] = m0; g_pl[b][c][0] = l0;
        g_pm[b][c][1] = m1; g_pl[b][c][1] = l1;
    }
}

// ---------------- kernel 2: merge partials, build pooled vectors ----------------
__global__ __launch_bounds__(256) void combine_pass(
    const float* __restrict__ tokens, const int* __restrict__ lengths)
{
    const int b = blockIdx.x, t = threadIdx.x;
    const int h = blockIdx.y * 256 + t;
    __shared__ float w0c[NCHUNK], w1c[NCHUNK];
    if (t == 0) {
        float M0 = -INFINITY, M1 = -INFINITY;
        for (int c = 0; c < NCHUNK; c++) {
            M0 = fmaxf(M0, g_pm[b][c][0]);
            M1 = fmaxf(M1, g_pm[b][c][1]);
        }
        float L0 = 0.f, L1 = 0.f;
        for (int c = 0; c < NCHUNK; c++) {
            L0 += g_pl[b][c][0] * __expf(g_pm[b][c][0] - M0);
            L1 += g_pl[b][c][1] * __expf(g_pm[b][c][1] - M1);
        }
        float iL0 = 1.f / L0, iL1 = 1.f / L1;
        for (int c = 0; c < NCHUNK; c++) {
            w0c[c] = __expf(g_pm[b][c][0] - M0) * iL0;
            w1c[c] = __expf(g_pm[b][c][1] - M1) * iL1;
        }
    }
    __syncthreads();
    const float inv_len = 1.f / (float)lengths[b];
    float sm = 0.f, mx = -INFINITY, mn = INFINITY, a0 = 0.f, a1 = 0.f;
#pragma unroll 4
    for (int c = 0; c < NCHUNK; c++) {
        sm += g_psum[b][c][h];
        mx = fmaxf(mx, g_pmax[b][c][h]);
        mn = fminf(mn, g_pmin[b][c][h]);
        a0 = fmaf(g_pacc0[b][c][h], w0c[c], a0);
        a1 = fmaf(g_pacc1[b][c][h], w1c[c], a1);
    }
    g_pooled[0][b][h]         = sm * inv_len;
    g_pooled[0][b][H + h]     = mx;
    g_pooled[0][b][2 * H + h] = mn;
    g_pooled[1][b][h]         = a0;
    g_pooled[1][b][H + h]     = a1;
    g_pooled[1][b][2 * H + h] = tokens[(size_t)b * (SEQ + 1) * H + h];  // clf
}

// ---------------- split-K GEMM: block-internal k-reduction, 6 deterministic slots ----
template <int K, int KC, bool LAYERA>
__global__ __launch_bounds__(256) void gemm_part(
    const float* __restrict__ W0, const float* __restrict__ W1)
{
    __shared__ __align__(16) char smemBuf[32768];  // union: sP then sAcc
    float (*sP)[20] = (float (*)[20])smemBuf;
    float4 (*sAcc)[16][16] = (float4 (*)[16][16])smemBuf;  // [warp][m][jq]

    const int br = blockIdx.z;
    const int j0 = blockIdx.x * 64;
    const int k0 = blockIdx.y * KC;
    const int t  = threadIdx.x;
    const float* W = br ? W1 : W0;
    const float* P = LAYERA ? &g_pooled[br][0][0] : &g_hid[br][0][0];

    for (int idx = t; idx < BATCH * KC; idx += 256) {
        int m = idx / KC, k = idx % KC;
        sP[k][m] = P[(size_t)m * K + k0 + k];
    }
    __syncthreads();

    const int jq = t & 15;
    const int jj = jq * 4;
    const int kg = t >> 4;                 // 0..15
    const int kb = kg * (KC / 16);
    float4 acc[BATCH];
#pragma unroll
    for (int m = 0; m < BATCH; m++) acc[m] = make_float4(0.f, 0.f, 0.f, 0.f);

    const float* Wp = W + (size_t)(k0 + kb) * H + j0 + jj;
#pragma unroll 4
    for (int k = 0; k < KC / 16; k++) {
        const float4 w = *(const float4*)(Wp + (size_t)k * H);
        const float* prow = &sP[kb + k][0];
#pragma unroll
        for (int m4 = 0; m4 < BATCH; m4 += 4) {
            const float4 pv = *(const float4*)(prow + m4);
            float pm[4] = {pv.x, pv.y, pv.z, pv.w};
#pragma unroll
            for (int u = 0; u < 4; u++) {
                acc[m4 + u].x = fmaf(pm[u], w.x, acc[m4 + u].x);
                acc[m4 + u].y = fmaf(pm[u], w.y, acc[m4 + u].y);
                acc[m4 + u].z = fmaf(pm[u], w.z, acc[m4 + u].z);
                acc[m4 + u].w = fmaf(pm[u], w.w, acc[m4 + u].w);
            }
        }
    }

    // pair-reduce the 2 k-groups within each warp (lanes L <-> L+16 share jq)
#pragma unroll
    for (int m = 0; m < BATCH; m++) {
        acc[m].x += __shfl_xor_sync(0xffffffffu, acc[m].x, 16);
        acc[m].y += __shfl_xor_sync(0xffffffffu, acc[m].y, 16);
        acc[m].z += __shfl_xor_sync(0xffffffffu, acc[m].z, 16);
        acc[m].w += __shfl_xor_sync(0xffffffffu, acc[m].w, 16);
    }
    __syncthreads();  // done reading sP
    const int wrp = t >> 5, lane = t & 31;
    if (lane < 16) {
#pragma unroll
        for (int m = 0; m < BATCH; m++) sAcc[wrp][m][lane] = acc[m];
    }
    __syncthreads();

    // final: thread t -> (m = t>>4, jq2 = t&15), sum over 8 warps
    const int m = t >> 4, jq2 = t & 15;
    float4 s = make_float4(0.f, 0.f, 0.f, 0.f);
#pragma unroll
    for (int w = 0; w < 8; w++) {
        float4 u = sAcc[w][m][jq2];
        s.x += u.x; s.y += u.y; s.z += u.z; s.w += u.w;
    }
    float* part = LAYERA ? &g_partA[br][blockIdx.y][0][0] : &g_partB[br][blockIdx.y][0][0];
    *(float4*)&part[(size_t)m * H + j0 + jq2 * 4] = s;
}

// ---------------- reduce 6 slots + bias (+GELU) ----------------
__global__ __launch_bounds__(256) void act_pass(
    const float* __restrict__ b1a, const float* __restrict__ b2a)
{
    const int id = blockIdx.x * 256 + threadIdx.x;  // 2*16*768
    const int j  = id % H;
    const int m  = (id / H) & (BATCH - 1);
    const int br = id / (H * BATCH);
    float s = (br ? b2a : b1a)[j];
#pragma unroll
    for (int sl = 0; sl < KSPLIT; sl++) s += g_partA[br][sl][m][j];
    g_hid[br][m][j] = 0.5f * s * (1.f + erff(s * 0.7071067811865476f));
}

__global__ __launch_bounds__(256) void final_pass(
    const float* __restrict__ b1b, const float* __restrict__ b2b,
    float* __restrict__ out)
{
    const int id = blockIdx.x * 256 + threadIdx.x;
    const int j  = id % H;
    const int m  = (id / H) & (BATCH - 1);
    const int br = id / (H * BATCH);
    float s = (br ? b2b : b1b)[j];
#pragma unroll
    for (int sl = 0; sl < KSPLIT; sl++) s += g_partB[br][sl][m][j];
    out[(size_t)m * (2 * H) + br * H + j] = s;
}

// ---------------- launch ----------------
extern "C" void kernel_launch(void* const* d_in, const int* in_sizes, int n_in,
                              void* d_out, int out_size)
{
    const float* tokens = (const float*)d_in[0];
    const int*   lengths= (const int*)  d_in[1];
    const float* q      = (const float*)d_in[2];
    const float* ln_g   = (const float*)d_in[3];
    const float* ln_b   = (const float*)d_in[4];
    const float* w1a    = (const float*)d_in[5];
    const float* b1a    = (const float*)d_in[6];
    const float* w1b    = (const float*)d_in[7];
    const float* b1b    = (const float*)d_in[8];
    const float* w2a    = (const float*)d_in[9];
    const float* b2a    = (const float*)d_in[10];
    const float* w2b    = (const float*)d_in[11];
    const float* b2b    = (const float*)d_in[12];
    float* out = (float*)d_out;

    main_pass<<<dim3(NCHUNK, BATCH), NT>>>(tokens, lengths, q, ln_g, ln_b);
    combine_pass<<<dim3(BATCH, 3), 256>>>(tokens, lengths);
    gemm_part<3 * H, 3 * H / KSPLIT, true ><<<dim3(H / 64, KSPLIT, 2), 256>>>(w1a, w2a);
    act_pass<<<(2 * BATCH * H) / 256, 256>>>(b1a, b2a);
    gemm_part<H, H / KSPLIT, false><<<dim3(H / 64, KSPLIT, 2), 256>>>(w1b, w2b);
    final_pass<<<(2 * BATCH * H) / 256, 256>>>(b1b, b2b, out);
}